// round 11
// baseline (speedup 1.0000x reference)
#include <cuda_runtime.h>
#include <cstdint>
#include <cstddef>

#define NN 50000
#define DD 128
#define BM 128
#define ST 36            // smem row stride (words): conflict-free fragment access
#define CHUNK 512
#define NCHUNK 98        // ceil(50000/512)
#define PADN (NCHUNK * CHUNK)   // 50176
#define RSN (NN + 1)
#define NE 500000

// ---- Scratch (allocation-free rule: device globals) ----
__device__ float g_Wh_chem[NN * DD];
__device__ float g_Wh_elec[NN * DD];
__device__ float g_h0[NN * DD];       // chem aggregation
__device__ float g_h1[NN * DD];       // elec aggregation
__device__ int   g_deg[2 * PADN];
__device__ int   g_local[2 * PADN];
__device__ int   g_ctot[2 * NCHUNK];
__device__ int   g_coff[2 * NCHUNK];
__device__ int   g_rs[2 * RSN];
__device__ int   g_cur[2 * NN];
__device__ int   g_csr[2 * NE];

__device__ __forceinline__ uint32_t f2tf32(float f) {
    uint32_t r;
    asm("cvt.rna.tf32.f32 %0, %1;" : "=r"(r) : "f"(f));
    return r;
}

__device__ __forceinline__ void mma_tf32(float c[4], const uint32_t a[4], const uint32_t b[2]) {
    asm volatile(
        "mma.sync.aligned.m16n8k8.row.col.f32.tf32.tf32.f32 "
        "{%0,%1,%2,%3}, {%4,%5,%6,%7}, {%8,%9}, {%0,%1,%2,%3};"
        : "+f"(c[0]), "+f"(c[1]), "+f"(c[2]), "+f"(c[3])
        : "r"(a[0]), "r"(a[1]), "r"(a[2]), "r"(a[3]), "r"(b[0]), "r"(b[1]));
}

// Dynamic smem: As[2][128][ST] | Ws[4][128][ST]
#define AS_WORDS (2 * 128 * ST)
#define WS_WORDS (4 * 128 * ST)
#define SMEM_BYTES ((AS_WORDS + WS_WORDS) * 4)

// C[M,128] = (A (+A2))[M,128] @ W^T + bias (+ extra).
__global__ __launch_bounds__(256, 2)
void gemm_tf32_kernel(const float* __restrict__ A, const float* __restrict__ A2,
                      const float* __restrict__ W, const float* __restrict__ bias,
                      float* __restrict__ C, const float* __restrict__ extra,
                      int M)
{
    extern __shared__ uint32_t smem[];
    uint32_t* As = smem;
    uint32_t* Ws = smem + AS_WORDS;

    const int tid  = threadIdx.x;
    const int lane = tid & 31;
    const int w    = tid >> 5;
    const int wm   = w & 3;
    const int wn   = w >> 2;
    const int mw   = wm * 32;
    const int nw   = wn * 64;
    const int gid  = lane >> 2;
    const int tig  = lane & 3;
    const int bm   = blockIdx.x * BM;

    // Prologue: all of W (128x128) into Ws, tf32, row-major
    #pragma unroll
    for (int i = 0; i < 16; i++) {
        int g   = tid + 256 * i;
        int c   = g >> 10;
        int row = (g >> 3) & 127;
        int qc  = g & 7;
        float4 vb = *(const float4*)(W + (size_t)row * DD + c * 32 + qc * 4);
        uint4 sv;
        sv.x = f2tf32(vb.x); sv.y = f2tf32(vb.y);
        sv.z = f2tf32(vb.z); sv.w = f2tf32(vb.w);
        *(uint4*)&Ws[(size_t)c * 128 * ST + row * ST + qc * 4] = sv;
    }

    float4 av[4];
    #pragma unroll
    for (int i = 0; i < 4; i++) {
        int g = tid + 256 * i, row = g >> 3, qc = g & 7, ar = bm + row;
        av[i] = make_float4(0.f, 0.f, 0.f, 0.f);
        if (ar < M) {
            av[i] = *(const float4*)(A + (size_t)ar * DD + qc * 4);
            if (A2) {
                float4 v2 = *(const float4*)(A2 + (size_t)ar * DD + qc * 4);
                av[i].x += v2.x; av[i].y += v2.y; av[i].z += v2.z; av[i].w += v2.w;
            }
        }
    }
    #pragma unroll
    for (int i = 0; i < 4; i++) {
        int g = tid + 256 * i, row = g >> 3, qc = g & 7;
        uint4 sv;
        sv.x = f2tf32(av[i].x); sv.y = f2tf32(av[i].y);
        sv.z = f2tf32(av[i].z); sv.w = f2tf32(av[i].w);
        *(uint4*)&As[row * ST + qc * 4] = sv;
    }
    __syncthreads();

    float acc[2][8][4];
    #pragma unroll
    for (int mt = 0; mt < 2; mt++)
        #pragma unroll
        for (int nt = 0; nt < 8; nt++)
            #pragma unroll
            for (int q = 0; q < 4; q++) acc[mt][nt][q] = 0.0f;

    #pragma unroll
    for (int c = 0; c < 4; c++) {
        if (c < 3) {
            #pragma unroll
            for (int i = 0; i < 4; i++) {
                int g = tid + 256 * i, row = g >> 3, qc = g & 7, ar = bm + row;
                av[i] = make_float4(0.f, 0.f, 0.f, 0.f);
                if (ar < M) {
                    av[i] = *(const float4*)(A + (size_t)ar * DD + (c + 1) * 32 + qc * 4);
                    if (A2) {
                        float4 v2 = *(const float4*)(A2 + (size_t)ar * DD + (c + 1) * 32 + qc * 4);
                        av[i].x += v2.x; av[i].y += v2.y; av[i].z += v2.z; av[i].w += v2.w;
                    }
                }
            }
        }
        const uint32_t* Ab = As + (size_t)(c & 1) * 128 * ST;
        const uint32_t* Wc = Ws + (size_t)c * 128 * ST;
        #pragma unroll
        for (int ks = 0; ks < 4; ks++) {
            const int k8 = ks * 8;
            uint32_t a[2][4], b[8][2];
            #pragma unroll
            for (int mt = 0; mt < 2; mt++) {
                int r0 = mw + mt * 16 + gid;
                a[mt][0] = Ab[r0 * ST + k8 + tig];
                a[mt][1] = Ab[(r0 + 8) * ST + k8 + tig];
                a[mt][2] = Ab[r0 * ST + k8 + tig + 4];
                a[mt][3] = Ab[(r0 + 8) * ST + k8 + tig + 4];
            }
            #pragma unroll
            for (int nt = 0; nt < 8; nt++) {
                int cc = nw + nt * 8 + gid;
                b[nt][0] = Wc[cc * ST + k8 + tig];
                b[nt][1] = Wc[cc * ST + k8 + tig + 4];
            }
            #pragma unroll
            for (int mt = 0; mt < 2; mt++)
                #pragma unroll
                for (int nt = 0; nt < 8; nt++)
                    mma_tf32(acc[mt][nt], a[mt], b[nt]);
        }
        if (c < 3) {
            uint32_t* Anext = As + (size_t)((c + 1) & 1) * 128 * ST;
            #pragma unroll
            for (int i = 0; i < 4; i++) {
                int g = tid + 256 * i, row = g >> 3, qc = g & 7;
                uint4 sv;
                sv.x = f2tf32(av[i].x); sv.y = f2tf32(av[i].y);
                sv.z = f2tf32(av[i].z); sv.w = f2tf32(av[i].w);
                *(uint4*)&Anext[row * ST + qc * 4] = sv;
            }
            __syncthreads();
        }
    }

    #pragma unroll
    for (int mt = 0; mt < 2; mt++) {
        #pragma unroll
        for (int half = 0; half < 2; half++) {
            int r = bm + mw + mt * 16 + gid + half * 8;
            if (r >= M) continue;
            #pragma unroll
            for (int nt = 0; nt < 8; nt++) {
                int col = nw + nt * 8 + tig * 2;
                float2 o;
                o.x = acc[mt][nt][half * 2 + 0] + bias[col];
                o.y = acc[mt][nt][half * 2 + 1] + bias[col + 1];
                if (extra) {
                    float2 e = *(const float2*)(extra + (size_t)r * DD + col);
                    o.x += e.x; o.y += e.y;
                }
                *(float2*)(C + (size_t)r * DD + col) = o;
            }
        }
    }
}

// ---- CSR build (proven chain) ----
__global__ __launch_bounds__(256)
void hist_kernel(const int* __restrict__ dst_c, const int* __restrict__ dst_e,
                 int nC, int nTot)
{
    int i = blockIdx.x * 256 + threadIdx.x;
    if (i >= nTot) return;
    int* cnt;
    if (i < nC) cnt = &g_deg[dst_c[i]];
    else        cnt = &g_deg[PADN + dst_e[i - nC]];
    asm volatile("red.global.add.u32 [%0], %1;" :: "l"(cnt), "r"(1) : "memory");
}

__global__ __launch_bounds__(512)
void scan_chunks_kernel(int N)
{
    const int et   = blockIdx.y;
    const int lane = threadIdx.x & 31;
    const int wid  = threadIdx.x >> 5;
    int n = blockIdx.x * CHUNK + threadIdx.x;
    int d = (n < N) ? g_deg[et * PADN + n] : 0;

    int incl = d;
    #pragma unroll
    for (int o = 1; o < 32; o <<= 1) {
        int t = __shfl_up_sync(0xffffffffu, incl, o);
        if (lane >= o) incl += t;
    }
    __shared__ int wtot[16];
    if (lane == 31) wtot[wid] = incl;
    __syncthreads();
    if (wid == 0) {
        int v = (lane < 16) ? wtot[lane] : 0;
        int wi = v;
        #pragma unroll
        for (int o = 1; o < 16; o <<= 1) {
            int t = __shfl_up_sync(0xffffffffu, wi, o);
            if (lane >= o) wi += t;
        }
        if (lane < 16) wtot[lane] = wi - v;
    }
    __syncthreads();
    int base = wtot[wid];
    if (n < N) g_local[et * PADN + n] = base + incl - d;
    if (wid == 15 && lane == 31) g_ctot[et * NCHUNK + blockIdx.x] = base + incl;
}

__global__ __launch_bounds__(64)
void scan_totals_kernel()
{
    const int et   = threadIdx.x >> 5;
    const int lane = threadIdx.x & 31;
    int carry = 0;
    for (int it = 0; it < (NCHUNK + 31) / 32; it++) {
        int idx = it * 32 + lane;
        int v = (idx < NCHUNK) ? g_ctot[et * NCHUNK + idx] : 0;
        int incl = v;
        #pragma unroll
        for (int o = 1; o < 32; o <<= 1) {
            int t = __shfl_up_sync(0xffffffffu, incl, o);
            if (lane >= o) incl += t;
        }
        if (idx < NCHUNK) g_coff[et * NCHUNK + idx] = carry + incl - v;
        carry += __shfl_sync(0xffffffffu, incl, 31);
    }
}

__global__ __launch_bounds__(256)
void rowstart_kernel(int N, int nEc, int nEe)
{
    int n = blockIdx.x * 256 + threadIdx.x;
    if (n > N) return;
    #pragma unroll
    for (int et = 0; et < 2; et++) {
        int v;
        if (n == N) v = et ? nEe : nEc;
        else v = g_coff[et * NCHUNK + (n >> 9)] + g_local[et * PADN + n];
        g_rs[et * RSN + n] = v;
        if (n < N) g_cur[et * NN + n] = v;
    }
}

__global__ __launch_bounds__(256)
void place_kernel(const int* __restrict__ src_c, const int* __restrict__ dst_c,
                  const int* __restrict__ src_e, const int* __restrict__ dst_e,
                  int nC, int nE_)
{
    int t = blockIdx.x * 256 + threadIdx.x;
    int nPairC = (nC + 1) >> 1;
    int nPairE = (nE_ + 1) >> 1;
    if (t < nPairC) {
        int e0 = 2 * t, e1 = 2 * t + 1;
        int d0 = dst_c[e0];
        int s0 = src_c[e0];
        int d1 = -1, s1 = 0;
        if (e1 < nC) { d1 = dst_c[e1]; s1 = src_c[e1]; }
        int p0 = atomicAdd(&g_cur[d0], 1);
        int p1 = (d1 >= 0) ? atomicAdd(&g_cur[d1], 1) : -1;
        g_csr[p0] = s0;
        if (p1 >= 0) g_csr[p1] = s1;
    } else if (t < nPairC + nPairE) {
        int u = t - nPairC;
        int e0 = 2 * u, e1 = 2 * u + 1;
        int d0 = dst_e[e0];
        int s0 = src_e[e0];
        int d1 = -1, s1 = 0;
        if (e1 < nE_) { d1 = dst_e[e1]; s1 = src_e[e1]; }
        int p0 = atomicAdd(&g_cur[NN + d0], 1);
        int p1 = (d1 >= 0) ? atomicAdd(&g_cur[NN + d1], 1) : -1;
        g_csr[NE + p0] = s0;
        if (p1 >= 0) g_csr[NE + p1] = s1;
    }
}

// ---- Gather aggregation for one etype: warp per node, fp32 rows, MLP=4 ----
__global__ __launch_bounds__(256)
void aggregate_kernel(int N, int et, const float* __restrict__ Wh,
                      float* __restrict__ hout)
{
    int warp = (int)((blockIdx.x * (unsigned)blockDim.x + threadIdx.x) >> 5);
    int lane = threadIdx.x & 31;
    if (warp >= N) return;

    int beg = __ldg(&g_rs[et * RSN + warp]);
    int end = __ldg(&g_rs[et * RSN + warp + 1]);
    const int* csr = g_csr + (size_t)et * NE;

    float4 acc = make_float4(0.f, 0.f, 0.f, 0.f);

    int i = beg;
    for (; i + 3 < end; i += 4) {
        int s0 = __ldg(csr + i);
        int s1 = __ldg(csr + i + 1);
        int s2 = __ldg(csr + i + 2);
        int s3 = __ldg(csr + i + 3);
        float4 v0 = __ldg((const float4*)(Wh + (size_t)s0 * DD) + lane);
        float4 v1 = __ldg((const float4*)(Wh + (size_t)s1 * DD) + lane);
        float4 v2 = __ldg((const float4*)(Wh + (size_t)s2 * DD) + lane);
        float4 v3 = __ldg((const float4*)(Wh + (size_t)s3 * DD) + lane);
        acc.x += (v0.x + v1.x) + (v2.x + v3.x);
        acc.y += (v0.y + v1.y) + (v2.y + v3.y);
        acc.z += (v0.z + v1.z) + (v2.z + v3.z);
        acc.w += (v0.w + v1.w) + (v2.w + v3.w);
    }
    for (; i < end; i++) {
        int s0 = __ldg(csr + i);
        float4 v0 = __ldg((const float4*)(Wh + (size_t)s0 * DD) + lane);
        acc.x += v0.x; acc.y += v0.y; acc.z += v0.z; acc.w += v0.w;
    }
    *((float4*)(hout + (size_t)warp * DD) + lane) = acc;
}

extern "C" void kernel_launch(void* const* d_in, const int* in_sizes, int n_in,
                              void* d_out, int out_size)
{
    const float* feats   = (const float*)d_in[0];
    const float* W_chem  = (const float*)d_in[1];
    const float* b_chem  = (const float*)d_in[2];
    const float* W_elec  = (const float*)d_in[3];
    const float* b_elec  = (const float*)d_in[4];
    const float* W_out   = (const float*)d_in[5];
    const float* b_out   = (const float*)d_in[6];
    const int*   src_ch  = (const int*)d_in[7];
    const int*   dst_ch  = (const int*)d_in[8];
    const int*   src_el  = (const int*)d_in[9];
    const int*   dst_el  = (const int*)d_in[10];
    float*       out     = (float*)d_out;

    const int M       = in_sizes[0] / DD;   // 50000
    const int nE_chem = in_sizes[7];
    const int nE_elec = in_sizes[9];
    const int nTot    = nE_chem + nE_elec;

    float *wh_chem, *wh_elec, *h0, *h1;
    void  *degp;
    cudaGetSymbolAddress((void**)&wh_chem, g_Wh_chem);
    cudaGetSymbolAddress((void**)&wh_elec, g_Wh_elec);
    cudaGetSymbolAddress((void**)&h0,      g_h0);
    cudaGetSymbolAddress((void**)&h1,      g_h1);
    cudaGetSymbolAddress(&degp,            g_deg);

    cudaFuncSetAttribute(gemm_tf32_kernel,
                         cudaFuncAttributeMaxDynamicSharedMemorySize, SMEM_BYTES);

    // Host-side resources, created once outside capture.
    static cudaStream_t s1 = nullptr, s2 = nullptr, s3 = nullptr;
    static cudaEvent_t  evFork = nullptr, evCSR = nullptr, evChem = nullptr,
                        evElec = nullptr, evA0 = nullptr, evA1 = nullptr;
    if (s1 == nullptr) {
        cudaStreamCreateWithFlags(&s1, cudaStreamNonBlocking);
        cudaStreamCreateWithFlags(&s2, cudaStreamNonBlocking);
        cudaStreamCreateWithFlags(&s3, cudaStreamNonBlocking);
        cudaEventCreateWithFlags(&evFork, cudaEventDisableTiming);
        cudaEventCreateWithFlags(&evCSR,  cudaEventDisableTiming);
        cudaEventCreateWithFlags(&evChem, cudaEventDisableTiming);
        cudaEventCreateWithFlags(&evElec, cudaEventDisableTiming);
        cudaEventCreateWithFlags(&evA0,   cudaEventDisableTiming);
        cudaEventCreateWithFlags(&evA1,   cudaEventDisableTiming);
    }

    const int mblocks  = (M + BM - 1) / BM;
    const int agblocks = (M * 32 + 255) / 256;

    // Fork side streams off the main (captured) stream.
    cudaEventRecord(evFork, 0);
    cudaStreamWaitEvent(s1, evFork, 0);

    // s1: CSR build (uses only edge indices)
    cudaMemsetAsync(degp, 0, 2 * PADN * sizeof(int), s1);
    hist_kernel<<<(nTot + 255) / 256, 256, 0, s1>>>(dst_ch, dst_el, nE_chem, nTot);
    scan_chunks_kernel<<<dim3(NCHUNK, 2), 512, 0, s1>>>(M);
    scan_totals_kernel<<<1, 64, 0, s1>>>();
    rowstart_kernel<<<(M + 256) / 256, 256, 0, s1>>>(M, nE_chem, nE_elec);
    {
        int nPair = ((nE_chem + 1) >> 1) + ((nE_elec + 1) >> 1);
        place_kernel<<<(nPair + 255) / 256, 256, 0, s1>>>(src_ch, dst_ch, src_el, dst_el,
                                                          nE_chem, nE_elec);
    }
    cudaEventRecord(evCSR, s1);

    // main: GEMM chem, then GEMM elec
    gemm_tf32_kernel<<<mblocks, 256, SMEM_BYTES>>>(
        feats, nullptr, W_chem, b_chem, wh_chem, /*extra=*/nullptr, M);
    cudaEventRecord(evChem, 0);

    gemm_tf32_kernel<<<mblocks, 256, SMEM_BYTES>>>(
        feats, nullptr, W_elec, b_elec, wh_elec, /*extra=*/nullptr, M);
    cudaEventRecord(evElec, 0);

    // s2: aggregate chem — overlaps GEMM elec
    cudaStreamWaitEvent(s2, evChem, 0);
    cudaStreamWaitEvent(s2, evCSR, 0);
    aggregate_kernel<<<agblocks, 256, 0, s2>>>(M, 0, wh_chem, h0);
    cudaEventRecord(evA0, s2);

    // s3: aggregate elec
    cudaStreamWaitEvent(s3, evElec, 0);
    cudaStreamWaitEvent(s3, evCSR, 0);
    aggregate_kernel<<<agblocks, 256, 0, s3>>>(M, 1, wh_elec, h1);
    cudaEventRecord(evA1, s3);

    // main: K4 = (h0 + h1) @ W_out^T + b_out + Wh_elec
    cudaStreamWaitEvent(0, evA0, 0);
    cudaStreamWaitEvent(0, evA1, 0);
    gemm_tf32_kernel<<<mblocks, 256, SMEM_BYTES>>>(
        h0, h1, W_out, b_out, out, /*extra=*/wh_elec, M);
}

// round 12
// speedup vs baseline: 1.4706x; 1.4706x over previous
#include <cuda_runtime.h>
#include <cstdint>
#include <cstddef>

#define NN 50000
#define DD 128
#define BM 128
#define ST 36            // smem row stride (words): conflict-free fragment access
#define CHUNK 512
#define NCHUNK 98        // ceil(50000/512)
#define PADN (NCHUNK * CHUNK)   // 50176
#define RSN (NN + 1)
#define NE 500000

// ---- Scratch (allocation-free rule: device globals) ----
__device__ float g_Wh_chem[NN * DD];
__device__ float g_Wh_elec[NN * DD];
__device__ float g_h[NN * DD];
__device__ int   g_deg[2 * PADN];
__device__ int   g_local[2 * PADN];
__device__ int   g_ctot[2 * NCHUNK];
__device__ int   g_coff[2 * NCHUNK];
__device__ int   g_rs[2 * RSN];
__device__ int   g_cur[2 * NN];
__device__ int   g_csr[2 * NE];

__device__ __forceinline__ uint32_t f2tf32(float f) {
    uint32_t r;
    asm("cvt.rna.tf32.f32 %0, %1;" : "=r"(r) : "f"(f));
    return r;
}

__device__ __forceinline__ void mma_tf32(float c[4], const uint32_t a[4], const uint32_t b[2]) {
    asm volatile(
        "mma.sync.aligned.m16n8k8.row.col.f32.tf32.tf32.f32 "
        "{%0,%1,%2,%3}, {%4,%5,%6,%7}, {%8,%9}, {%0,%1,%2,%3};"
        : "+f"(c[0]), "+f"(c[1]), "+f"(c[2]), "+f"(c[3])
        : "r"(a[0]), "r"(a[1]), "r"(a[2]), "r"(a[3]), "r"(b[0]), "r"(b[1]));
}

// Dynamic smem: As[2][128][ST] | Ws[2][128][ST]  (both double-buffered per K-chunk)
#define BUF_WORDS (128 * ST)
#define AS_WORDS (2 * BUF_WORDS)
#define WS_WORDS (2 * BUF_WORDS)
#define SMEM_BYTES ((AS_WORDS + WS_WORDS) * 4)   // 73728 B -> 2 CTAs = 147KB/SM

// C[M,128] = A[M,128] @ W^T + bias (+ extra). blockIdx.y selects param set.
__global__ __launch_bounds__(256, 2)
void gemm_tf32_kernel(const float* __restrict__ A,
                      const float* __restrict__ W0, const float* __restrict__ b0,
                      float* __restrict__ C0,
                      const float* __restrict__ W1, const float* __restrict__ b1,
                      float* __restrict__ C1,
                      const float* __restrict__ extra,
                      int M)
{
    extern __shared__ uint32_t smem[];
    uint32_t* As = smem;
    uint32_t* Ws = smem + AS_WORDS;

    const float* W    = W0;
    const float* bias = b0;
    float*       C    = C0;
    const float* ex   = extra;
    if (blockIdx.y == 1) { W = W1; bias = b1; C = C1; ex = nullptr; }

    const int tid  = threadIdx.x;
    const int lane = tid & 31;
    const int w    = tid >> 5;
    const int wm   = w & 3;
    const int wn   = w >> 2;
    const int mw   = wm * 32;
    const int nw   = wn * 64;
    const int gid  = lane >> 2;
    const int tig  = lane & 3;
    const int bm   = blockIdx.x * BM;

    // Per-thread tile coordinates for staging (4 float4 per tensor per chunk)
    const int srow = tid >> 1;                 // 0..127 (2 threads per row)
    // each thread covers float4 slots {qc0, qc0+2} ... use g-based scheme instead:
    // g = tid + 256*i, row = g>>3, qc = g&7

    float4 av[4], wv[4];
    // Load chunk 0 of A and W
    #pragma unroll
    for (int i = 0; i < 4; i++) {
        int g = tid + 256 * i, row = g >> 3, qc = g & 7, ar = bm + row;
        av[i] = make_float4(0.f, 0.f, 0.f, 0.f);
        if (ar < M) av[i] = *(const float4*)(A + (size_t)ar * DD + qc * 4);
        wv[i] = *(const float4*)(W + (size_t)row * DD + qc * 4);
    }
    #pragma unroll
    for (int i = 0; i < 4; i++) {
        int g = tid + 256 * i, row = g >> 3, qc = g & 7;
        uint4 sa, sw;
        sa.x = f2tf32(av[i].x); sa.y = f2tf32(av[i].y);
        sa.z = f2tf32(av[i].z); sa.w = f2tf32(av[i].w);
        sw.x = f2tf32(wv[i].x); sw.y = f2tf32(wv[i].y);
        sw.z = f2tf32(wv[i].z); sw.w = f2tf32(wv[i].w);
        *(uint4*)&As[row * ST + qc * 4] = sa;
        *(uint4*)&Ws[row * ST + qc * 4] = sw;
    }
    __syncthreads();

    float acc[2][8][4];
    #pragma unroll
    for (int mt = 0; mt < 2; mt++)
        #pragma unroll
        for (int nt = 0; nt < 8; nt++)
            #pragma unroll
            for (int q = 0; q < 4; q++) acc[mt][nt][q] = 0.0f;

    #pragma unroll
    for (int c = 0; c < 4; c++) {
        if (c < 3) {
            #pragma unroll
            for (int i = 0; i < 4; i++) {
                int g = tid + 256 * i, row = g >> 3, qc = g & 7, ar = bm + row;
                av[i] = make_float4(0.f, 0.f, 0.f, 0.f);
                if (ar < M) av[i] = *(const float4*)(A + (size_t)ar * DD + (c + 1) * 32 + qc * 4);
                wv[i] = *(const float4*)(W + (size_t)row * DD + (c + 1) * 32 + qc * 4);
            }
        }
        const uint32_t* Ab = As + (size_t)(c & 1) * BUF_WORDS;
        const uint32_t* Wc = Ws + (size_t)(c & 1) * BUF_WORDS;
        #pragma unroll
        for (int ks = 0; ks < 4; ks++) {
            const int k8 = ks * 8;
            uint32_t a[2][4], b[8][2];
            #pragma unroll
            for (int mt = 0; mt < 2; mt++) {
                int r0 = mw + mt * 16 + gid;
                a[mt][0] = Ab[r0 * ST + k8 + tig];
                a[mt][1] = Ab[(r0 + 8) * ST + k8 + tig];
                a[mt][2] = Ab[r0 * ST + k8 + tig + 4];
                a[mt][3] = Ab[(r0 + 8) * ST + k8 + tig + 4];
            }
            #pragma unroll
            for (int nt = 0; nt < 8; nt++) {
                int cc = nw + nt * 8 + gid;
                b[nt][0] = Wc[cc * ST + k8 + tig];
                b[nt][1] = Wc[cc * ST + k8 + tig + 4];
            }
            #pragma unroll
            for (int mt = 0; mt < 2; mt++)
                #pragma unroll
                for (int nt = 0; nt < 8; nt++)
                    mma_tf32(acc[mt][nt], a[mt], b[nt]);
        }
        if (c < 3) {
            uint32_t* An = As + (size_t)((c + 1) & 1) * BUF_WORDS;
            uint32_t* Wn = Ws + (size_t)((c + 1) & 1) * BUF_WORDS;
            __syncthreads();   // ensure all reads of current buffers done before overwrite
            #pragma unroll
            for (int i = 0; i < 4; i++) {
                int g = tid + 256 * i, row = g >> 3, qc = g & 7;
                uint4 sa, sw;
                sa.x = f2tf32(av[i].x); sa.y = f2tf32(av[i].y);
                sa.z = f2tf32(av[i].z); sa.w = f2tf32(av[i].w);
                sw.x = f2tf32(wv[i].x); sw.y = f2tf32(wv[i].y);
                sw.z = f2tf32(wv[i].z); sw.w = f2tf32(wv[i].w);
                *(uint4*)&An[row * ST + qc * 4] = sa;
                *(uint4*)&Wn[row * ST + qc * 4] = sw;
            }
            __syncthreads();
        }
    }

    #pragma unroll
    for (int mt = 0; mt < 2; mt++) {
        #pragma unroll
        for (int half = 0; half < 2; half++) {
            int r = bm + mw + mt * 16 + gid + half * 8;
            if (r >= M) continue;
            #pragma unroll
            for (int nt = 0; nt < 8; nt++) {
                int col = nw + nt * 8 + tig * 2;
                float2 o;
                o.x = acc[mt][nt][half * 2 + 0] + bias[col];
                o.y = acc[mt][nt][half * 2 + 1] + bias[col + 1];
                if (ex) {
                    float2 e = *(const float2*)(ex + (size_t)r * DD + col);
                    o.x += e.x; o.y += e.y;
                }
                *(float2*)(C + (size_t)r * DD + col) = o;
            }
        }
    }
}

// ---- CSR build (proven chain) ----
__global__ __launch_bounds__(256)
void hist_kernel(const int* __restrict__ dst_c, const int* __restrict__ dst_e,
                 int nC, int nTot)
{
    int i = blockIdx.x * 256 + threadIdx.x;
    if (i >= nTot) return;
    int* cnt;
    if (i < nC) cnt = &g_deg[dst_c[i]];
    else        cnt = &g_deg[PADN + dst_e[i - nC]];
    asm volatile("red.global.add.u32 [%0], %1;" :: "l"(cnt), "r"(1) : "memory");
}

__global__ __launch_bounds__(512)
void scan_chunks_kernel(int N)
{
    const int et   = blockIdx.y;
    const int lane = threadIdx.x & 31;
    const int wid  = threadIdx.x >> 5;
    int n = blockIdx.x * CHUNK + threadIdx.x;
    int d = (n < N) ? g_deg[et * PADN + n] : 0;

    int incl = d;
    #pragma unroll
    for (int o = 1; o < 32; o <<= 1) {
        int t = __shfl_up_sync(0xffffffffu, incl, o);
        if (lane >= o) incl += t;
    }
    __shared__ int wtot[16];
    if (lane == 31) wtot[wid] = incl;
    __syncthreads();
    if (wid == 0) {
        int v = (lane < 16) ? wtot[lane] : 0;
        int wi = v;
        #pragma unroll
        for (int o = 1; o < 16; o <<= 1) {
            int t = __shfl_up_sync(0xffffffffu, wi, o);
            if (lane >= o) wi += t;
        }
        if (lane < 16) wtot[lane] = wi - v;
    }
    __syncthreads();
    int base = wtot[wid];
    if (n < N) g_local[et * PADN + n] = base + incl - d;
    if (wid == 15 && lane == 31) g_ctot[et * NCHUNK + blockIdx.x] = base + incl;
}

__global__ __launch_bounds__(64)
void scan_totals_kernel()
{
    const int et   = threadIdx.x >> 5;
    const int lane = threadIdx.x & 31;
    int carry = 0;
    for (int it = 0; it < (NCHUNK + 31) / 32; it++) {
        int idx = it * 32 + lane;
        int v = (idx < NCHUNK) ? g_ctot[et * NCHUNK + idx] : 0;
        int incl = v;
        #pragma unroll
        for (int o = 1; o < 32; o <<= 1) {
            int t = __shfl_up_sync(0xffffffffu, incl, o);
            if (lane >= o) incl += t;
        }
        if (idx < NCHUNK) g_coff[et * NCHUNK + idx] = carry + incl - v;
        carry += __shfl_sync(0xffffffffu, incl, 31);
    }
}

__global__ __launch_bounds__(256)
void rowstart_kernel(int N, int nEc, int nEe)
{
    int n = blockIdx.x * 256 + threadIdx.x;
    if (n > N) return;
    #pragma unroll
    for (int et = 0; et < 2; et++) {
        int v;
        if (n == N) v = et ? nEe : nEc;
        else v = g_coff[et * NCHUNK + (n >> 9)] + g_local[et * PADN + n];
        g_rs[et * RSN + n] = v;
        if (n < N) g_cur[et * NN + n] = v;
    }
}

__global__ __launch_bounds__(256)
void place_kernel(const int* __restrict__ src_c, const int* __restrict__ dst_c,
                  const int* __restrict__ src_e, const int* __restrict__ dst_e,
                  int nC, int nE_)
{
    int t = blockIdx.x * 256 + threadIdx.x;
    int nPairC = (nC + 1) >> 1;
    int nPairE = (nE_ + 1) >> 1;
    if (t < nPairC) {
        int e0 = 2 * t, e1 = 2 * t + 1;
        int d0 = dst_c[e0];
        int s0 = src_c[e0];
        int d1 = -1, s1 = 0;
        if (e1 < nC) { d1 = dst_c[e1]; s1 = src_c[e1]; }
        int p0 = atomicAdd(&g_cur[d0], 1);
        int p1 = (d1 >= 0) ? atomicAdd(&g_cur[d1], 1) : -1;
        g_csr[p0] = s0;
        if (p1 >= 0) g_csr[p1] = s1;
    } else if (t < nPairC + nPairE) {
        int u = t - nPairC;
        int e0 = 2 * u, e1 = 2 * u + 1;
        int d0 = dst_e[e0];
        int s0 = src_e[e0];
        int d1 = -1, s1 = 0;
        if (e1 < nE_) { d1 = dst_e[e1]; s1 = src_e[e1]; }
        int p0 = atomicAdd(&g_cur[NN + d0], 1);
        int p1 = (d1 >= 0) ? atomicAdd(&g_cur[NN + d1], 1) : -1;
        g_csr[NE + p0] = s0;
        if (p1 >= 0) g_csr[NE + p1] = s1;
    }
}

// ---- Gather aggregation: one warp per node, both etypes, fp32 rows, MLP=4 ----
__global__ __launch_bounds__(256)
void aggregate_kernel(int N)
{
    int warp = (int)((blockIdx.x * (unsigned)blockDim.x + threadIdx.x) >> 5);
    int lane = threadIdx.x & 31;
    if (warp >= N) return;

    int beg0 = __ldg(&g_rs[warp]);
    int end0 = __ldg(&g_rs[warp + 1]);
    int beg1 = __ldg(&g_rs[RSN + warp]);
    int end1 = __ldg(&g_rs[RSN + warp + 1]);

    float4 acc = make_float4(0.f, 0.f, 0.f, 0.f);

    #pragma unroll
    for (int et = 0; et < 2; et++) {
        const float* Wh  = et ? g_Wh_elec : g_Wh_chem;
        const int*   csr = g_csr + (size_t)et * NE;
        int beg = et ? beg1 : beg0;
        int end = et ? end1 : end0;
        int i = beg;
        for (; i + 3 < end; i += 4) {
            int s0 = __ldg(csr + i);
            int s1 = __ldg(csr + i + 1);
            int s2 = __ldg(csr + i + 2);
            int s3 = __ldg(csr + i + 3);
            float4 v0 = __ldg((const float4*)(Wh + (size_t)s0 * DD) + lane);
            float4 v1 = __ldg((const float4*)(Wh + (size_t)s1 * DD) + lane);
            float4 v2 = __ldg((const float4*)(Wh + (size_t)s2 * DD) + lane);
            float4 v3 = __ldg((const float4*)(Wh + (size_t)s3 * DD) + lane);
            acc.x += (v0.x + v1.x) + (v2.x + v3.x);
            acc.y += (v0.y + v1.y) + (v2.y + v3.y);
            acc.z += (v0.z + v1.z) + (v2.z + v3.z);
            acc.w += (v0.w + v1.w) + (v2.w + v3.w);
        }
        for (; i < end; i++) {
            int s0 = __ldg(csr + i);
            float4 v0 = __ldg((const float4*)(Wh + (size_t)s0 * DD) + lane);
            acc.x += v0.x; acc.y += v0.y; acc.z += v0.z; acc.w += v0.w;
        }
    }
    *((float4*)(g_h + (size_t)warp * DD) + lane) = acc;
}

extern "C" void kernel_launch(void* const* d_in, const int* in_sizes, int n_in,
                              void* d_out, int out_size)
{
    const float* feats   = (const float*)d_in[0];
    const float* W_chem  = (const float*)d_in[1];
    const float* b_chem  = (const float*)d_in[2];
    const float* W_elec  = (const float*)d_in[3];
    const float* b_elec  = (const float*)d_in[4];
    const float* W_out   = (const float*)d_in[5];
    const float* b_out   = (const float*)d_in[6];
    const int*   src_ch  = (const int*)d_in[7];
    const int*   dst_ch  = (const int*)d_in[8];
    const int*   src_el  = (const int*)d_in[9];
    const int*   dst_el  = (const int*)d_in[10];
    float*       out     = (float*)d_out;

    const int M       = in_sizes[0] / DD;   // 50000
    const int nE_chem = in_sizes[7];
    const int nE_elec = in_sizes[9];
    const int nTot    = nE_chem + nE_elec;

    float *wh_chem, *wh_elec, *hbuf;
    void  *degp;
    cudaGetSymbolAddress((void**)&wh_chem, g_Wh_chem);
    cudaGetSymbolAddress((void**)&wh_elec, g_Wh_elec);
    cudaGetSymbolAddress((void**)&hbuf,    g_h);
    cudaGetSymbolAddress(&degp,            g_deg);

    cudaFuncSetAttribute(gemm_tf32_kernel,
                         cudaFuncAttributeMaxDynamicSharedMemorySize, SMEM_BYTES);

    static cudaStream_t s1 = nullptr;
    static cudaEvent_t  evFork = nullptr, evJoin = nullptr;
    if (s1 == nullptr) {
        cudaStreamCreateWithFlags(&s1, cudaStreamNonBlocking);
        cudaEventCreateWithFlags(&evFork, cudaEventDisableTiming);
        cudaEventCreateWithFlags(&evJoin, cudaEventDisableTiming);
    }

    const int mblocks = (M + BM - 1) / BM;

    // Fork: s1 branches off the main (captured) stream.
    cudaEventRecord(evFork, 0);
    cudaStreamWaitEvent(s1, evFork, 0);

    // Branch A (main stream): K1 dual GEMM — Wh_chem & Wh_elec
    gemm_tf32_kernel<<<dim3(mblocks, 2), 256, SMEM_BYTES>>>(
        feats, W_chem, b_chem, wh_chem,
        W_elec, b_elec, wh_elec,
        /*extra=*/nullptr, M);

    // Branch B (s1): CSR build — co-schedulable now (GEMM leaves 81KB smem/SM)
    cudaMemsetAsync(degp, 0, 2 * PADN * sizeof(int), s1);
    hist_kernel<<<(nTot + 255) / 256, 256, 0, s1>>>(dst_ch, dst_el, nE_chem, nTot);
    scan_chunks_kernel<<<dim3(NCHUNK, 2), 512, 0, s1>>>(M);
    scan_totals_kernel<<<1, 64, 0, s1>>>();
    rowstart_kernel<<<(M + 256) / 256, 256, 0, s1>>>(M, nE_chem, nE_elec);
    {
        int nPair = ((nE_chem + 1) >> 1) + ((nE_elec + 1) >> 1);
        place_kernel<<<(nPair + 255) / 256, 256, 0, s1>>>(src_ch, dst_ch, src_el, dst_el,
                                                          nE_chem, nE_elec);
    }

    // Join
    cudaEventRecord(evJoin, s1);
    cudaStreamWaitEvent(0, evJoin, 0);

    // Gather aggregation
    aggregate_kernel<<<(M * 32 + 255) / 256, 256>>>(M);

    // K4: out = h @ W_out^T + b_out + Wh_elec
    gemm_tf32_kernel<<<dim3(mblocks, 1), 256, SMEM_BYTES>>>(
        hbuf, W_out, b_out, out,
        nullptr, nullptr, nullptr,
        /*extra=*/wh_elec, M);
}

// round 13
// speedup vs baseline: 1.5301x; 1.0404x over previous
#include <cuda_runtime.h>
#include <cuda_fp16.h>
#include <cstdint>
#include <cstddef>

#define NN 50000
#define DD 128
#define BM 128
#define ST 36            // smem row stride (words): conflict-free fragment access
#define CHUNK 512
#define NCHUNK 98        // ceil(50000/512)
#define PADN (NCHUNK * CHUNK)   // 50176
#define RSN (NN + 1)
#define NE 500000

// ---- Scratch (allocation-free rule: device globals) ----
__device__ float  g_Wh_elec[NN * DD];       // fp32 (exact, for K4 extra)
__device__ __half g_Wh16[2 * NN * DD];      // fp16 gather copies (chem, elec)
__device__ float  g_h[NN * DD];
__device__ int    g_deg[2 * PADN];
__device__ int    g_local[2 * PADN];
__device__ int    g_ctot[2 * NCHUNK];
__device__ int    g_coff[2 * NCHUNK];
__device__ int    g_rs[2 * RSN];
__device__ int    g_cur[2 * NN];
__device__ int    g_csr[2 * NE];

__device__ __forceinline__ uint32_t f2tf32(float f) {
    uint32_t r;
    asm("cvt.rna.tf32.f32 %0, %1;" : "=r"(r) : "f"(f));
    return r;
}

__device__ __forceinline__ void mma_tf32(float c[4], const uint32_t a[4], const uint32_t b[2]) {
    asm volatile(
        "mma.sync.aligned.m16n8k8.row.col.f32.tf32.tf32.f32 "
        "{%0,%1,%2,%3}, {%4,%5,%6,%7}, {%8,%9}, {%0,%1,%2,%3};"
        : "+f"(c[0]), "+f"(c[1]), "+f"(c[2]), "+f"(c[3])
        : "r"(a[0]), "r"(a[1]), "r"(a[2]), "r"(a[3]), "r"(b[0]), "r"(b[1]));
}

// Dynamic smem: As[2][128][ST] | Ws[2][128][ST]  (double-buffered per K-chunk)
#define BUF_WORDS (128 * ST)
#define AS_WORDS (2 * BUF_WORDS)
#define WS_WORDS (2 * BUF_WORDS)
#define SMEM_BYTES ((AS_WORDS + WS_WORDS) * 4)   // 73728 B -> 2 CTAs/SM

// C[M,128] = A[M,128] @ W^T + bias (+ extra). blockIdx.y selects param set.
// C may be null; C16, if set, receives an fp16 copy.
__global__ __launch_bounds__(256, 2)
void gemm_tf32_kernel(const float* __restrict__ A,
                      const float* __restrict__ W0, const float* __restrict__ b0,
                      float* __restrict__ C0, __half* __restrict__ C16_0,
                      const float* __restrict__ W1, const float* __restrict__ b1,
                      float* __restrict__ C1, __half* __restrict__ C16_1,
                      const float* __restrict__ extra,
                      int M)
{
    extern __shared__ uint32_t smem[];
    uint32_t* As = smem;
    uint32_t* Ws = smem + AS_WORDS;

    const float* W    = W0;
    const float* bias = b0;
    float*       C    = C0;
    __half*      C16  = C16_0;
    const float* ex   = extra;
    if (blockIdx.y == 1) { W = W1; bias = b1; C = C1; C16 = C16_1; ex = nullptr; }

    const int tid  = threadIdx.x;
    const int lane = tid & 31;
    const int w    = tid >> 5;
    const int wm   = w & 3;
    const int wn   = w >> 2;
    const int mw   = wm * 32;
    const int nw   = wn * 64;
    const int gid  = lane >> 2;
    const int tig  = lane & 3;
    const int bm   = blockIdx.x * BM;

    float4 av[4], wv[4];
    #pragma unroll
    for (int i = 0; i < 4; i++) {
        int g = tid + 256 * i, row = g >> 3, qc = g & 7, ar = bm + row;
        av[i] = make_float4(0.f, 0.f, 0.f, 0.f);
        if (ar < M) av[i] = *(const float4*)(A + (size_t)ar * DD + qc * 4);
        wv[i] = *(const float4*)(W + (size_t)row * DD + qc * 4);
    }
    #pragma unroll
    for (int i = 0; i < 4; i++) {
        int g = tid + 256 * i, row = g >> 3, qc = g & 7;
        uint4 sa, sw;
        sa.x = f2tf32(av[i].x); sa.y = f2tf32(av[i].y);
        sa.z = f2tf32(av[i].z); sa.w = f2tf32(av[i].w);
        sw.x = f2tf32(wv[i].x); sw.y = f2tf32(wv[i].y);
        sw.z = f2tf32(wv[i].z); sw.w = f2tf32(wv[i].w);
        *(uint4*)&As[row * ST + qc * 4] = sa;
        *(uint4*)&Ws[row * ST + qc * 4] = sw;
    }
    __syncthreads();

    float acc[2][8][4];
    #pragma unroll
    for (int mt = 0; mt < 2; mt++)
        #pragma unroll
        for (int nt = 0; nt < 8; nt++)
            #pragma unroll
            for (int q = 0; q < 4; q++) acc[mt][nt][q] = 0.0f;

    #pragma unroll
    for (int c = 0; c < 4; c++) {
        if (c < 3) {
            #pragma unroll
            for (int i = 0; i < 4; i++) {
                int g = tid + 256 * i, row = g >> 3, qc = g & 7, ar = bm + row;
                av[i] = make_float4(0.f, 0.f, 0.f, 0.f);
                if (ar < M) av[i] = *(const float4*)(A + (size_t)ar * DD + (c + 1) * 32 + qc * 4);
                wv[i] = *(const float4*)(W + (size_t)row * DD + (c + 1) * 32 + qc * 4);
            }
        }
        const uint32_t* Ab = As + (size_t)(c & 1) * BUF_WORDS;
        const uint32_t* Wc = Ws + (size_t)(c & 1) * BUF_WORDS;
        #pragma unroll
        for (int ks = 0; ks < 4; ks++) {
            const int k8 = ks * 8;
            uint32_t a[2][4], b[8][2];
            #pragma unroll
            for (int mt = 0; mt < 2; mt++) {
                int r0 = mw + mt * 16 + gid;
                a[mt][0] = Ab[r0 * ST + k8 + tig];
                a[mt][1] = Ab[(r0 + 8) * ST + k8 + tig];
                a[mt][2] = Ab[r0 * ST + k8 + tig + 4];
                a[mt][3] = Ab[(r0 + 8) * ST + k8 + tig + 4];
            }
            #pragma unroll
            for (int nt = 0; nt < 8; nt++) {
                int cc = nw + nt * 8 + gid;
                b[nt][0] = Wc[cc * ST + k8 + tig];
                b[nt][1] = Wc[cc * ST + k8 + tig + 4];
            }
            #pragma unroll
            for (int mt = 0; mt < 2; mt++)
                #pragma unroll
                for (int nt = 0; nt < 8; nt++)
                    mma_tf32(acc[mt][nt], a[mt], b[nt]);
        }
        if (c < 3) {
            uint32_t* An = As + (size_t)((c + 1) & 1) * BUF_WORDS;
            uint32_t* Wn = Ws + (size_t)((c + 1) & 1) * BUF_WORDS;
            __syncthreads();
            #pragma unroll
            for (int i = 0; i < 4; i++) {
                int g = tid + 256 * i, row = g >> 3, qc = g & 7;
                uint4 sa, sw;
                sa.x = f2tf32(av[i].x); sa.y = f2tf32(av[i].y);
                sa.z = f2tf32(av[i].z); sa.w = f2tf32(av[i].w);
                sw.x = f2tf32(wv[i].x); sw.y = f2tf32(wv[i].y);
                sw.z = f2tf32(wv[i].z); sw.w = f2tf32(wv[i].w);
                *(uint4*)&An[row * ST + qc * 4] = sa;
                *(uint4*)&Wn[row * ST + qc * 4] = sw;
            }
            __syncthreads();
        }
    }

    #pragma unroll
    for (int mt = 0; mt < 2; mt++) {
        #pragma unroll
        for (int half = 0; half < 2; half++) {
            int r = bm + mw + mt * 16 + gid + half * 8;
            if (r >= M) continue;
            #pragma unroll
            for (int nt = 0; nt < 8; nt++) {
                int col = nw + nt * 8 + tig * 2;
                float2 o;
                o.x = acc[mt][nt][half * 2 + 0] + bias[col];
                o.y = acc[mt][nt][half * 2 + 1] + bias[col + 1];
                if (ex) {
                    float2 e = *(const float2*)(ex + (size_t)r * DD + col);
                    o.x += e.x; o.y += e.y;
                }
                if (C)   *(float2*)(C + (size_t)r * DD + col) = o;
                if (C16) *(__half2*)(C16 + (size_t)r * DD + col) = __float22half2_rn(o);
            }
        }
    }
}

// ---- CSR build (proven chain) ----
__global__ __launch_bounds__(256)
void hist_kernel(const int* __restrict__ dst_c, const int* __restrict__ dst_e,
                 int nC, int nTot)
{
    int i = blockIdx.x * 256 + threadIdx.x;
    if (i >= nTot) return;
    int* cnt;
    if (i < nC) cnt = &g_deg[dst_c[i]];
    else        cnt = &g_deg[PADN + dst_e[i - nC]];
    asm volatile("red.global.add.u32 [%0], %1;" :: "l"(cnt), "r"(1) : "memory");
}

__global__ __launch_bounds__(512)
void scan_chunks_kernel(int N)
{
    const int et   = blockIdx.y;
    const int lane = threadIdx.x & 31;
    const int wid  = threadIdx.x >> 5;
    int n = blockIdx.x * CHUNK + threadIdx.x;
    int d = (n < N) ? g_deg[et * PADN + n] : 0;

    int incl = d;
    #pragma unroll
    for (int o = 1; o < 32; o <<= 1) {
        int t = __shfl_up_sync(0xffffffffu, incl, o);
        if (lane >= o) incl += t;
    }
    __shared__ int wtot[16];
    if (lane == 31) wtot[wid] = incl;
    __syncthreads();
    if (wid == 0) {
        int v = (lane < 16) ? wtot[lane] : 0;
        int wi = v;
        #pragma unroll
        for (int o = 1; o < 16; o <<= 1) {
            int t = __shfl_up_sync(0xffffffffu, wi, o);
            if (lane >= o) wi += t;
        }
        if (lane < 16) wtot[lane] = wi - v;
    }
    __syncthreads();
    int base = wtot[wid];
    if (n < N) g_local[et * PADN + n] = base + incl - d;
    if (wid == 15 && lane == 31) g_ctot[et * NCHUNK + blockIdx.x] = base + incl;
}

__global__ __launch_bounds__(64)
void scan_totals_kernel()
{
    const int et   = threadIdx.x >> 5;
    const int lane = threadIdx.x & 31;
    int carry = 0;
    for (int it = 0; it < (NCHUNK + 31) / 32; it++) {
        int idx = it * 32 + lane;
        int v = (idx < NCHUNK) ? g_ctot[et * NCHUNK + idx] : 0;
        int incl = v;
        #pragma unroll
        for (int o = 1; o < 32; o <<= 1) {
            int t = __shfl_up_sync(0xffffffffu, incl, o);
            if (lane >= o) incl += t;
        }
        if (idx < NCHUNK) g_coff[et * NCHUNK + idx] = carry + incl - v;
        carry += __shfl_sync(0xffffffffu, incl, 31);
    }
}

__global__ __launch_bounds__(256)
void rowstart_kernel(int N, int nEc, int nEe)
{
    int n = blockIdx.x * 256 + threadIdx.x;
    if (n > N) return;
    #pragma unroll
    for (int et = 0; et < 2; et++) {
        int v;
        if (n == N) v = et ? nEe : nEc;
        else v = g_coff[et * NCHUNK + (n >> 9)] + g_local[et * PADN + n];
        g_rs[et * RSN + n] = v;
        if (n < N) g_cur[et * NN + n] = v;
    }
}

__global__ __launch_bounds__(256)
void place_kernel(const int* __restrict__ src_c, const int* __restrict__ dst_c,
                  const int* __restrict__ src_e, const int* __restrict__ dst_e,
                  int nC, int nE_)
{
    int t = blockIdx.x * 256 + threadIdx.x;
    int nPairC = (nC + 1) >> 1;
    int nPairE = (nE_ + 1) >> 1;
    if (t < nPairC) {
        int e0 = 2 * t, e1 = 2 * t + 1;
        int d0 = dst_c[e0];
        int s0 = src_c[e0];
        int d1 = -1, s1 = 0;
        if (e1 < nC) { d1 = dst_c[e1]; s1 = src_c[e1]; }
        int p0 = atomicAdd(&g_cur[d0], 1);
        int p1 = (d1 >= 0) ? atomicAdd(&g_cur[d1], 1) : -1;
        g_csr[p0] = s0;
        if (p1 >= 0) g_csr[p1] = s1;
    } else if (t < nPairC + nPairE) {
        int u = t - nPairC;
        int e0 = 2 * u, e1 = 2 * u + 1;
        int d0 = dst_e[e0];
        int s0 = src_e[e0];
        int d1 = -1, s1 = 0;
        if (e1 < nE_) { d1 = dst_e[e1]; s1 = src_e[e1]; }
        int p0 = atomicAdd(&g_cur[NN + d0], 1);
        int p1 = (d1 >= 0) ? atomicAdd(&g_cur[NN + d1], 1) : -1;
        g_csr[NE + p0] = s0;
        if (p1 >= 0) g_csr[NE + p1] = s1;
    }
}

// ---- Gather aggregation: warp/node, fp16 rows (256B), fp32 accumulate, MLP=4 ----
// Lane owns 4 halves: uint2 (8B) load at half-offset lane*4; float4 store at lane*4.
__global__ __launch_bounds__(256)
void aggregate_kernel(int N)
{
    int warp = (int)((blockIdx.x * (unsigned)blockDim.x + threadIdx.x) >> 5);
    int lane = threadIdx.x & 31;
    if (warp >= N) return;

    int beg0 = __ldg(&g_rs[warp]);
    int end0 = __ldg(&g_rs[warp + 1]);
    int beg1 = __ldg(&g_rs[RSN + warp]);
    int end1 = __ldg(&g_rs[RSN + warp + 1]);

    float acc[4] = {0.f, 0.f, 0.f, 0.f};

    #pragma unroll
    for (int et = 0; et < 2; et++) {
        const __half* Wh  = g_Wh16 + (size_t)et * NN * DD;
        const int*    csr = g_csr + (size_t)et * NE;
        int beg = et ? beg1 : beg0;
        int end = et ? end1 : end0;
        int i = beg;
        for (; i + 3 < end; i += 4) {
            int s0 = __ldg(csr + i);
            int s1 = __ldg(csr + i + 1);
            int s2 = __ldg(csr + i + 2);
            int s3 = __ldg(csr + i + 3);
            uint2 r0 = __ldg((const uint2*)(Wh + (size_t)s0 * DD) + lane);
            uint2 r1 = __ldg((const uint2*)(Wh + (size_t)s1 * DD) + lane);
            uint2 r2 = __ldg((const uint2*)(Wh + (size_t)s2 * DD) + lane);
            uint2 r3 = __ldg((const uint2*)(Wh + (size_t)s3 * DD) + lane);
            float2 a0 = __half22float2(*(const __half2*)&r0.x);
            float2 b0 = __half22float2(*(const __half2*)&r0.y);
            float2 a1 = __half22float2(*(const __half2*)&r1.x);
            float2 b1 = __half22float2(*(const __half2*)&r1.y);
            float2 a2 = __half22float2(*(const __half2*)&r2.x);
            float2 b2 = __half22float2(*(const __half2*)&r2.y);
            float2 a3 = __half22float2(*(const __half2*)&r3.x);
            float2 b3 = __half22float2(*(const __half2*)&r3.y);
            acc[0] += (a0.x + a1.x) + (a2.x + a3.x);
            acc[1] += (a0.y + a1.y) + (a2.y + a3.y);
            acc[2] += (b0.x + b1.x) + (b2.x + b3.x);
            acc[3] += (b0.y + b1.y) + (b2.y + b3.y);
        }
        for (; i < end; i++) {
            int s0 = __ldg(csr + i);
            uint2 r0 = __ldg((const uint2*)(Wh + (size_t)s0 * DD) + lane);
            float2 a0 = __half22float2(*(const __half2*)&r0.x);
            float2 b0 = __half22float2(*(const __half2*)&r0.y);
            acc[0] += a0.x; acc[1] += a0.y;
            acc[2] += b0.x; acc[3] += b0.y;
        }
    }
    *((float4*)(g_h + (size_t)warp * DD) + lane) =
        make_float4(acc[0], acc[1], acc[2], acc[3]);
}

extern "C" void kernel_launch(void* const* d_in, const int* in_sizes, int n_in,
                              void* d_out, int out_size)
{
    const float* feats   = (const float*)d_in[0];
    const float* W_chem  = (const float*)d_in[1];
    const float* b_chem  = (const float*)d_in[2];
    const float* W_elec  = (const float*)d_in[3];
    const float* b_elec  = (const float*)d_in[4];
    const float* W_out   = (const float*)d_in[5];
    const float* b_out   = (const float*)d_in[6];
    const int*   src_ch  = (const int*)d_in[7];
    const int*   dst_ch  = (const int*)d_in[8];
    const int*   src_el  = (const int*)d_in[9];
    const int*   dst_el  = (const int*)d_in[10];
    float*       out     = (float*)d_out;

    const int M       = in_sizes[0] / DD;   // 50000
    const int nE_chem = in_sizes[7];
    const int nE_elec = in_sizes[9];
    const int nTot    = nE_chem + nE_elec;

    float  *wh_elec, *hbuf;
    __half *wh16;
    void   *degp;
    cudaGetSymbolAddress((void**)&wh_elec, g_Wh_elec);
    cudaGetSymbolAddress((void**)&wh16,    g_Wh16);
    cudaGetSymbolAddress((void**)&hbuf,    g_h);
    cudaGetSymbolAddress(&degp,            g_deg);

    cudaFuncSetAttribute(gemm_tf32_kernel,
                         cudaFuncAttributeMaxDynamicSharedMemorySize, SMEM_BYTES);

    static cudaStream_t s1 = nullptr;
    static cudaEvent_t  evFork = nullptr, evJoin = nullptr;
    if (s1 == nullptr) {
        cudaStreamCreateWithFlags(&s1, cudaStreamNonBlocking);
        cudaEventCreateWithFlags(&evFork, cudaEventDisableTiming);
        cudaEventCreateWithFlags(&evJoin, cudaEventDisableTiming);
    }

    const int mblocks = (M + BM - 1) / BM;

    // Fork: s1 branches off the main (captured) stream.
    cudaEventRecord(evFork, 0);
    cudaStreamWaitEvent(s1, evFork, 0);

    // Branch A (main): K1 dual GEMM — chem (fp16 only), elec (fp32 + fp16)
    gemm_tf32_kernel<<<dim3(mblocks, 2), 256, SMEM_BYTES>>>(
        feats,
        W_chem, b_chem, /*C0=*/nullptr, /*C16_0=*/wh16,
        W_elec, b_elec, /*C1=*/wh_elec, /*C16_1=*/wh16 + (size_t)NN * DD,
        /*extra=*/nullptr, M);

    // Branch B (s1): CSR build
    cudaMemsetAsync(degp, 0, 2 * PADN * sizeof(int), s1);
    hist_kernel<<<(nTot + 255) / 256, 256, 0, s1>>>(dst_ch, dst_el, nE_chem, nTot);
    scan_chunks_kernel<<<dim3(NCHUNK, 2), 512, 0, s1>>>(M);
    scan_totals_kernel<<<1, 64, 0, s1>>>();
    rowstart_kernel<<<(M + 256) / 256, 256, 0, s1>>>(M, nE_chem, nE_elec);
    {
        int nPair = ((nE_chem + 1) >> 1) + ((nE_elec + 1) >> 1);
        place_kernel<<<(nPair + 255) / 256, 256, 0, s1>>>(src_ch, dst_ch, src_el, dst_el,
                                                          nE_chem, nE_elec);
    }

    // Join
    cudaEventRecord(evJoin, s1);
    cudaStreamWaitEvent(0, evJoin, 0);

    // Gather aggregation (fp16 rows, half the LTS bytes)
    aggregate_kernel<<<(M * 32 + 255) / 256, 256>>>(M);

    // K4: out = h @ W_out^T + b_out + Wh_elec (fp32 exact extra)
    gemm_tf32_kernel<<<dim3(mblocks, 1), 256, SMEM_BYTES>>>(
        hbuf,
        W_out, b_out, out, /*C16_0=*/nullptr,
        nullptr, nullptr, nullptr, nullptr,
        /*extra=*/wh_elec, M);
}